// round 9
// baseline (speedup 1.0000x reference)
#include <cuda_runtime.h>
#include <cstdint>

#define K 128
#define AT_NB 16
#define Z_NB 16

typedef unsigned long long ull;

// ---------------- persistent device scratch (no allocs allowed) ----------------
__device__ float g_A[K * K];      // A[i][j] = sum_o Wq[o,i]*Wk[o,j] / sqrt(128)
__device__ float g_M0[K * K];     // transposed [k][o]: inv_sqrt2*scale[o]*sum_c conv_w[o,c]*Wv[c,k]
__device__ float g_M1[K * K];     // transposed [k][o]: same with conv_w[o,128+c]
__device__ float g_tb[K];         // (conv_b-mean)*scale + beta
__device__ float g_w[65536 * 4];  // attention weights per (b,s)

// ---------------- packed f32x2 helpers ----------------
__device__ __forceinline__ ull pack_dup(float v) {
    unsigned u = __float_as_uint(v);
    ull r;
    asm("mov.b64 %0, {%1, %1};" : "=l"(r) : "r"(u));
    return r;
}
__device__ __forceinline__ void fma2(ull& acc, ull a, ull b) {
    asm("fma.rn.f32x2 %0, %1, %2, %0;" : "+l"(acc) : "l"(a), "l"(b));
}
__device__ __forceinline__ float f2lo(ull v) { return __uint_as_float((unsigned)v); }
__device__ __forceinline__ float f2hi(ull v) { return __uint_as_float((unsigned)(v >> 32)); }

// ---------------- setup: build A, M0t, M1t, tb ----------------
__global__ void setup_kernel(const float* __restrict__ Wq, const float* __restrict__ Wk,
                             const float* __restrict__ Wv, const float* __restrict__ conv_w,
                             const float* __restrict__ conv_b, const float* __restrict__ gamma,
                             const float* __restrict__ beta, const float* __restrict__ mean,
                             const float* __restrict__ var) {
    const int m = blockIdx.y;   // 0: A, 1: M0, 2: M1
    const int r = blockIdx.x;   // row index (i for A, o for M)
    const int t = threadIdx.x;  // 128 threads
    if (m == 0) {
        float acc = 0.f;
        for (int o = 0; o < K; ++o)
            acc += Wq[o * K + r] * Wk[o * K + t];
        g_A[r * K + t] = acc * 0.08838834764831845f;  // 1/sqrt(128)
    } else {
        __shared__ float cw[K];
        const float* src = conv_w + r * 256 + (m == 2 ? K : 0);
        cw[t] = src[t];
        __syncthreads();
        const float sc = gamma[r] * rsqrtf(var[r] + 1e-5f);
        float acc = 0.f;
        for (int c = 0; c < K; ++c)
            acc += cw[c] * Wv[c * K + t];
        const float val = acc * sc * 0.7071067811865476f;
        if (m == 1) {
            g_M0[t * K + r] = val;
            if (t == 0) g_tb[r] = (conv_b[r] - mean[r]) * sc + beta[r];
        } else {
            g_M1[t * K + r] = val;
        }
    }
}

// ---------------- attention weights: p = y@A, dots, softmax -> g_w ----------------
__global__ __launch_bounds__(256) void attn_kernel(const float* __restrict__ x,
                                                   const float* __restrict__ y, int B) {
    extern __shared__ float sm[];
    float* sA = sm;                // K*K       = 16384 floats
    float* sY = sA + K * K;        // AT_NB*K   =  2048
    float* sP = sY + AT_NB * K;    // AT_NB*K   =  2048
    float* sD = sP + AT_NB * K;    // AT_NB*16  =   256
    const int t = threadIdx.x;

    for (int i = t; i < K * K / 4; i += 256)
        ((float4*)sA)[i] = ((const float4*)g_A)[i];

    const int nchunk = B / AT_NB;
    for (int ch = blockIdx.x; ch < nchunk; ch += gridDim.x) {
        const int b0 = ch * AT_NB;
        __syncthreads();  // protect sY/sP/sA from reuse across iterations
        for (int i = t; i < AT_NB * K / 4; i += 256)
            ((float4*)sY)[i] = ((const float4*)(y + (size_t)b0 * K))[i];
        __syncthreads();

        // P = Y @ A : thread -> 4 j's (packed as 2 f32x2 lanes) x 2 b's
        {
            const int jj = (t & 31) * 4;
            const int bb0 = (t >> 5) * 2;
            ull a0x = 0, a0y = 0, a1x = 0, a1y = 0;
            const float* y0p = sY + bb0 * K;
            const float* y1p = y0p + K;
            for (int i = 0; i < K; ++i) {
                const ulonglong2 av = *(const ulonglong2*)(sA + i * K + jj);
                const ull Y0 = pack_dup(y0p[i]);
                const ull Y1 = pack_dup(y1p[i]);
                fma2(a0x, av.x, Y0);
                fma2(a0y, av.y, Y0);
                fma2(a1x, av.x, Y1);
                fma2(a1y, av.y, Y1);
            }
            ull* pp0 = (ull*)(sP + bb0 * K + jj);
            pp0[0] = a0x;
            pp0[1] = a0y;
            ull* pp1 = (ull*)(sP + (bb0 + 1) * K + jj);
            pp1[0] = a1x;
            pp1[1] = a1y;
        }
        __syncthreads();

        // partial dots: dot[bb][s] = p . x_s   (4 partials per dot)
        {
            const int q = t >> 2, part = t & 3;
            const int bb = q >> 2, s = q & 3;
            const float4* xr = (const float4*)(x + (((size_t)(b0 + bb)) * 4 + s) * K + part * 32);
            const float4* pr = (const float4*)(sP + bb * K + part * 32);
            float acc = 0.f;
#pragma unroll
            for (int j = 0; j < 8; ++j) {
                const float4 xv = xr[j];
                const float4 pv = pr[j];
                acc += xv.x * pv.x + xv.y * pv.y + xv.z * pv.z + xv.w * pv.w;
            }
            sD[q * 4 + part] = acc;
        }
        __syncthreads();

        if (t < AT_NB) {
            float dd[4];
#pragma unroll
            for (int s = 0; s < 4; ++s) {
                const float* p = sD + (t * 4 + s) * 4;
                dd[s] = (p[0] + p[1]) + (p[2] + p[3]);
            }
            const float mx = fmaxf(fmaxf(dd[0], dd[1]), fmaxf(dd[2], dd[3]));
            float e[4];
            float es = 0.f;
#pragma unroll
            for (int s = 0; s < 4; ++s) {
                e[s] = expf(dd[s] - mx);
                es += e[s];
            }
            const float inv = 1.f / es;
            float* wp = g_w + (size_t)(b0 + t) * 4;
#pragma unroll
            for (int s = 0; s < 4; ++s) wp[s] = e[s] * inv;
        }
    }
}

// ---------------- main z kernel: c-vectors + fused GEMV + BN + leaky ----------------
__global__ __launch_bounds__(512) void z_kernel(const float* __restrict__ x,
                                                float* __restrict__ out, int B) {
    extern __shared__ float sm[];
    float* sM0 = sm;                          // 16384 floats
    float* sM1 = sM0 + K * K;                 // 16384 floats
    float2* sCA = (float2*)(sM1 + K * K);     // Z_NB*K float2 (c0,c1)
    float2* sCB = sCA + Z_NB * K;             // Z_NB*K float2 (c2,c3)
    const int t = threadIdx.x;  // 512

    for (int i = t; i < K * K / 4; i += 512) {
        ((float4*)sM0)[i] = ((const float4*)g_M0)[i];
        ((float4*)sM1)[i] = ((const float4*)g_M1)[i];
    }
    const int o = t & 127;
    const int bbg = t >> 7;  // 0..3, each handles 4 consecutive b's
    const float tb = g_tb[o];

    const int nchunk = B / Z_NB;
    for (int ch = blockIdx.x; ch < nchunk; ch += gridDim.x) {
        const int b0 = ch * Z_NB;
        __syncthreads();
        // form c vectors: cA=(w0x0+w1x1, w0x0-w1x1), cB=(w2x2+w3x3, w2x2-w3x3)
        for (int idx = t; idx < Z_NB * K; idx += 512) {
            const int bb = idx >> 7, k = idx & 127;
            const float* xp = x + ((size_t)(b0 + bb)) * (4 * K) + k;
            const float x0 = xp[0], x1 = xp[K], x2 = xp[2 * K], x3 = xp[3 * K];
            const float* wp = g_w + (size_t)(b0 + bb) * 4;
            const float a0 = wp[0] * x0, a1 = wp[1] * x1;
            const float a2 = wp[2] * x2, a3 = wp[3] * x3;
            sCA[idx] = make_float2(a0 + a1, a0 - a1);
            sCB[idx] = make_float2(a2 + a3, a2 - a3);
        }
        __syncthreads();

        ull acc[4] = {0ull, 0ull, 0ull, 0ull};
        const float2* cA = sCA + (bbg * 4) * K;
        const float2* cB = sCB + (bbg * 4) * K;
        for (int k = 0; k < K; k += 4) {
            const float* m0p = sM0 + k * K + o;
            const float* m1p = sM1 + k * K + o;
            const ull M00 = pack_dup(m0p[0]);
            const ull M01 = pack_dup(m0p[K]);
            const ull M02 = pack_dup(m0p[2 * K]);
            const ull M03 = pack_dup(m0p[3 * K]);
            const ull M10 = pack_dup(m1p[0]);
            const ull M11 = pack_dup(m1p[K]);
            const ull M12 = pack_dup(m1p[2 * K]);
            const ull M13 = pack_dup(m1p[3 * K]);
#pragma unroll
            for (int i = 0; i < 4; ++i) {
                const ulonglong2* pa = (const ulonglong2*)(cA + i * K + k);
                const ulonglong2* pb = (const ulonglong2*)(cB + i * K + k);
                const ulonglong2 va0 = pa[0];
                const ulonglong2 va1 = pa[1];
                const ulonglong2 vb0 = pb[0];
                const ulonglong2 vb1 = pb[1];
                fma2(acc[i], M00, va0.x);
                fma2(acc[i], M01, va0.y);
                fma2(acc[i], M02, va1.x);
                fma2(acc[i], M03, va1.y);
                fma2(acc[i], M10, vb0.x);
                fma2(acc[i], M11, vb0.y);
                fma2(acc[i], M12, vb1.x);
                fma2(acc[i], M13, vb1.y);
            }
        }

        // epilogue: bias + leaky relu, write 8 consecutive j's (one 32B sector)
        float vals[8];
#pragma unroll
        for (int i = 0; i < 4; ++i) {
            float ze = f2lo(acc[i]) + tb;
            float zo = f2hi(acc[i]) + tb;
            ze = ze > 0.f ? ze : 0.01f * ze;
            zo = zo > 0.f ? zo : 0.01f * zo;
            vals[2 * i] = ze;
            vals[2 * i + 1] = zo;
        }
        const int b0g = b0 + bbg * 4;
        const int g = b0g >> 9;        // / 512
        const int d0 = b0g & 511;
        float* op = out + ((size_t)g * K + o) * 1024 + 2 * d0;
        ((float4*)op)[0] = make_float4(vals[0], vals[1], vals[2], vals[3]);
        ((float4*)op)[1] = make_float4(vals[4], vals[5], vals[6], vals[7]);
    }
}

// ---------------- launch ----------------
extern "C" void kernel_launch(void* const* d_in, const int* in_sizes, int n_in,
                              void* d_out, int out_size) {
    const float* x = (const float*)d_in[0];
    const float* y = (const float*)d_in[1];
    const float* Wq = (const float*)d_in[2];
    const float* Wk = (const float*)d_in[3];
    const float* Wv = (const float*)d_in[4];
    const float* conv_w = (const float*)d_in[5];
    const float* conv_b = (const float*)d_in[6];
    const float* gamma = (const float*)d_in[7];
    const float* beta = (const float*)d_in[8];
    const float* mean = (const float*)d_in[9];
    const float* var = (const float*)d_in[10];
    const int B = in_sizes[0] / (4 * K);

    const size_t attn_smem = (size_t)(K * K + AT_NB * K * 2 + AT_NB * 16) * sizeof(float);
    const size_t z_smem = (size_t)(2 * K * K) * sizeof(float) + (size_t)(2 * Z_NB * K) * sizeof(float2);
    cudaFuncSetAttribute(attn_kernel, cudaFuncAttributeMaxDynamicSharedMemorySize, (int)attn_smem);
    cudaFuncSetAttribute(z_kernel, cudaFuncAttributeMaxDynamicSharedMemorySize, (int)z_smem);

    setup_kernel<<<dim3(K, 3), K>>>(Wq, Wk, Wv, conv_w, conv_b, gamma, beta, mean, var);
    attn_kernel<<<296, 256, attn_smem>>>(x, y, B);
    z_kernel<<<148, 512, z_smem>>>(x, (float*)d_out, B);
}

// round 10
// speedup vs baseline: 1.1018x; 1.1018x over previous
#include <cuda_runtime.h>
#include <cstdint>

#define K 128

typedef unsigned long long ull;

// ---------------- persistent device scratch ----------------
__device__ float g_A[K * K];      // A[i][j] = sum_o Wq[o,i]*Wk[o,j] / sqrt(128)
__device__ float g_M0[K * K];     // [k][o] layout
__device__ float g_M1[K * K];     // [k][o] layout
__device__ float g_tb[K];         // (conv_b-mean)*scale + beta
__device__ float g_w[32768 * 4];  // attention weights per (b,s)

// ---------------- packed f32x2 helpers ----------------
__device__ __forceinline__ ull pack_dup(float v) {
    unsigned u = __float_as_uint(v);
    ull r;
    asm("mov.b64 %0, {%1, %1};" : "=l"(r) : "r"(u));
    return r;
}
__device__ __forceinline__ void fma2(ull& acc, ull a, ull b) {
    asm("fma.rn.f32x2 %0, %1, %2, %0;" : "+l"(acc) : "l"(a), "l"(b));
}
__device__ __forceinline__ float f2lo(ull v) { return __uint_as_float((unsigned)v); }
__device__ __forceinline__ float f2hi(ull v) { return __uint_as_float((unsigned)(v >> 32)); }

// ---------------- setup: build A, M0[k][o], M1[k][o], tb ----------------
__global__ __launch_bounds__(256) void setup_kernel(
    const float* __restrict__ Wq, const float* __restrict__ Wk, const float* __restrict__ Wv,
    const float* __restrict__ conv_w, const float* __restrict__ conv_b,
    const float* __restrict__ gamma, const float* __restrict__ beta,
    const float* __restrict__ mean, const float* __restrict__ var) {
    const int m = blockIdx.y;   // 0: A, 1: M0, 2: M1
    const int r = blockIdx.x;   // i for A, o for M
    const int t = threadIdx.x;  // 256
    const int j = t & 127, h = t >> 7;
    __shared__ float row[K];
    __shared__ float red[256];
    if (m == 0) {
        if (t < K) row[t] = Wq[t * K + r];
        __syncthreads();
        float acc = 0.f;
        const int o0 = h * 64;
#pragma unroll 8
        for (int o = 0; o < 64; ++o) acc += row[o0 + o] * Wk[(o0 + o) * K + j];
        red[t] = acc;
        __syncthreads();
        if (t < K) g_A[r * K + t] = (red[t] + red[t + 128]) * 0.08838834764831845f;
    } else {
        if (t < K) row[t] = conv_w[r * 256 + (m == 2 ? K : 0) + t];
        __syncthreads();
        float acc = 0.f;
        const int c0 = h * 64;
#pragma unroll 8
        for (int c = 0; c < 64; ++c) acc += row[c0 + c] * Wv[(c0 + c) * K + j];
        red[t] = acc;
        __syncthreads();
        if (t < K) {
            const float sc = gamma[r] * rsqrtf(var[r] + 1e-5f);
            const float val = (red[t] + red[t + 128]) * sc * 0.7071067811865476f;
            if (m == 1) {
                g_M0[t * K + r] = val;  // [k][o]
                if (t == 0) g_tb[r] = (conv_b[r] - mean[r]) * sc + beta[r];
            } else {
                g_M1[t * K + r] = val;
            }
        }
    }
}

// ---------------- attention: fused P-GEMM + dot + softmax ----------------
// chunk = 64 b. 8 warps = (jh 0..3: 32-j block) x (ih 0..1: 64-i half).
// lane covers b=lane and b=lane+32. dot is linear in P partials -> per-warp
// partial dots reduced across the 8 warps in smem.
__global__ __launch_bounds__(256, 2) void attn_kernel(const float* __restrict__ x,
                                                      const float* __restrict__ y, int B) {
    extern __shared__ float sm[];
    float* sA = sm;              // 16384 floats
    float* sY = sA + 16384;      // [i][b] : 128*64 = 8192
    float* sD = sY + 8192;       // 8 warps * 64 b * 4 s = 2048
    const int t = threadIdx.x;
    const int lane = t & 31, w = t >> 5;
    const int jh = w & 3, ih = w >> 2;

    for (int i = t; i < 4096; i += 256) ((float4*)sA)[i] = ((const float4*)g_A)[i];

    const int nch = B >> 6;
    for (int ch = blockIdx.x; ch < nch; ch += gridDim.x) {
        const int b0 = ch << 6;
        __syncthreads();
        // stage y transposed: sY[i][b]
        {
            const int b = t >> 2, iq = t & 3;
            const float4* yp = (const float4*)(y + (size_t)(b0 + b) * K + iq * 32);
            float4 v[8];
#pragma unroll
            for (int q = 0; q < 8; ++q) v[q] = yp[q];
#pragma unroll
            for (int q = 0; q < 8; ++q) {
                const int i = iq * 32 + q * 4;
                sY[(i + 0) * 64 + b] = v[q].x;
                sY[(i + 1) * 64 + b] = v[q].y;
                sY[(i + 2) * 64 + b] = v[q].z;
                sY[(i + 3) * 64 + b] = v[q].w;
            }
        }
        __syncthreads();

        // P partial GEMM over this warp's (j-block, i-half)
        ull acc0[16], acc1[16];
#pragma unroll
        for (int p = 0; p < 16; ++p) { acc0[p] = 0; acc1[p] = 0; }
        {
            const float* Arow = sA + (ih * 64) * K + jh * 32;
            const float* Yrow = sY + (ih * 64) * 64;
#pragma unroll 2
            for (int i = 0; i < 64; ++i) {
                const ull y0 = pack_dup(Yrow[i * 64 + lane]);
                const ull y1 = pack_dup(Yrow[i * 64 + lane + 32]);
                const ulonglong2* ap = (const ulonglong2*)(Arow + i * K);
#pragma unroll
                for (int p = 0; p < 8; ++p) {
                    const ulonglong2 av = ap[p];
                    fma2(acc0[2 * p], av.x, y0);
                    fma2(acc0[2 * p + 1], av.y, y0);
                    fma2(acc1[2 * p], av.x, y1);
                    fma2(acc1[2 * p + 1], av.y, y1);
                }
            }
        }

        // partial dots with x over this j-block
        {
            float d0[4], d1[4];
            const float* xb0 = x + ((size_t)(b0 + lane)) * 4 * K + jh * 32;
#pragma unroll
            for (int s = 0; s < 4; ++s) {
                const ulonglong2* xp = (const ulonglong2*)(xb0 + s * K);
                ull da = 0;
#pragma unroll
                for (int p = 0; p < 8; ++p) {
                    const ulonglong2 xv = xp[p];
                    fma2(da, acc0[2 * p], xv.x);
                    fma2(da, acc0[2 * p + 1], xv.y);
                }
                d0[s] = f2lo(da) + f2hi(da);
            }
            const float* xb1 = x + ((size_t)(b0 + lane + 32)) * 4 * K + jh * 32;
#pragma unroll
            for (int s = 0; s < 4; ++s) {
                const ulonglong2* xp = (const ulonglong2*)(xb1 + s * K);
                ull da = 0;
#pragma unroll
                for (int p = 0; p < 8; ++p) {
                    const ulonglong2 xv = xp[p];
                    fma2(da, acc1[2 * p], xv.x);
                    fma2(da, acc1[2 * p + 1], xv.y);
                }
                d1[s] = f2lo(da) + f2hi(da);
            }
            ((float4*)sD)[w * 64 + lane] = make_float4(d0[0], d0[1], d0[2], d0[3]);
            ((float4*)sD)[w * 64 + lane + 32] = make_float4(d1[0], d1[1], d1[2], d1[3]);
        }
        __syncthreads();

        if (t < 64) {
            float4 s0 = make_float4(0.f, 0.f, 0.f, 0.f);
#pragma unroll
            for (int ww = 0; ww < 8; ++ww) {
                const float4 v = ((const float4*)sD)[ww * 64 + t];
                s0.x += v.x; s0.y += v.y; s0.z += v.z; s0.w += v.w;
            }
            const float mx = fmaxf(fmaxf(s0.x, s0.y), fmaxf(s0.z, s0.w));
            const float e0 = expf(s0.x - mx), e1 = expf(s0.y - mx);
            const float e2 = expf(s0.z - mx), e3 = expf(s0.w - mx);
            const float inv = 1.f / (e0 + e1 + e2 + e3);
            ((float4*)g_w)[b0 + t] = make_float4(e0 * inv, e1 * inv, e2 * inv, e3 * inv);
        }
    }
}

// ---------------- z kernel: c-vectors + GEMM + BN + leaky ----------------
// chunk = 32 b. 16 warps: warp w -> o-block [w*8, w*8+8). lane = b.
// sM0/sM1 [k][o] so LDS.128 broadcast gives f32x2 o-pairs directly.
__global__ __launch_bounds__(512) void z_kernel(const float* __restrict__ x,
                                                float* __restrict__ out, int B) {
    extern __shared__ float sm[];
    float* sM0 = sm;            // 16384
    float* sM1 = sM0 + 16384;   // 16384
    float4* sC = (float4*)(sM1 + 16384);  // [k][b] float4 (cA0,cA1,cB0,cB1): 128*32
    const int t = threadIdx.x;
    const int lane = t & 31, w = t >> 5;  // w: 0..15 (= kq in build phase)

    for (int i = t; i < 4096; i += 512) {
        ((float4*)sM0)[i] = ((const float4*)g_M0)[i];
        ((float4*)sM1)[i] = ((const float4*)g_M1)[i];
    }
    const int o0 = w * 8;
    float tb[8];
#pragma unroll
    for (int q = 0; q < 8; ++q) tb[q] = g_tb[o0 + q];

    const int nch = B >> 5;  // 1024
    float4 xv[8];
    float4 wv;
    int ch = blockIdx.x;
    if (ch < nch) {
        const float* xp = x + (size_t)((ch << 5) + lane) * 512 + w * 8;
#pragma unroll
        for (int s = 0; s < 4; ++s) {
            xv[2 * s] = *(const float4*)(xp + s * 128);
            xv[2 * s + 1] = *(const float4*)(xp + s * 128 + 4);
        }
        wv = ((const float4*)g_w)[(ch << 5) + lane];
    }

    for (; ch < nch; ch += gridDim.x) {
        const int b0 = ch << 5;
        __syncthreads();  // previous chunk's sC fully consumed
        // build c vectors from registers
        {
            const int kbase = w * 8;
#pragma unroll
            for (int j = 0; j < 8; ++j) {
                const float4 xa = xv[(j >> 2)];          // s=0 pair select below
                // gather x[s][j]: xv[2*s + (j>>2)] component (j&3)
                float xs[4];
#pragma unroll
                for (int s = 0; s < 4; ++s) {
                    const float4 v = xv[2 * s + (j >> 2)];
                    xs[s] = (j & 3) == 0 ? v.x : (j & 3) == 1 ? v.y : (j & 3) == 2 ? v.z : v.w;
                }
                (void)xa;
                const float a0 = wv.x * xs[0], a1 = wv.y * xs[1];
                const float a2 = wv.z * xs[2], a3 = wv.w * xs[3];
                sC[(kbase + j) * 32 + lane] = make_float4(a0 + a1, a0 - a1, a2 + a3, a2 - a3);
            }
        }
        __syncthreads();
        // prefetch next chunk's x/w while GEMM runs
        const int nx = ch + gridDim.x;
        if (nx < nch) {
            const float* xp = x + (size_t)((nx << 5) + lane) * 512 + w * 8;
#pragma unroll
            for (int s = 0; s < 4; ++s) {
                xv[2 * s] = *(const float4*)(xp + s * 128);
                xv[2 * s + 1] = *(const float4*)(xp + s * 128 + 4);
            }
            wv = ((const float4*)g_w)[(nx << 5) + lane];
        }

        ull accE[4] = {0, 0, 0, 0}, accO[4] = {0, 0, 0, 0};
#pragma unroll 4
        for (int k = 0; k < 128; ++k) {
            const float4 cv = sC[k * 32 + lane];
            const ull dA0 = pack_dup(cv.x), dA1 = pack_dup(cv.y);
            const ull dB0 = pack_dup(cv.z), dB1 = pack_dup(cv.w);
            const ulonglong2* m0 = (const ulonglong2*)(sM0 + k * 128 + o0);
            const ulonglong2* m1 = (const ulonglong2*)(sM1 + k * 128 + o0);
            const ulonglong2 m0a = m0[0], m0b = m0[1];
            const ulonglong2 m1a = m1[0], m1b = m1[1];
            fma2(accE[0], m0a.x, dA0); fma2(accE[1], m0a.y, dA0);
            fma2(accE[2], m0b.x, dA0); fma2(accE[3], m0b.y, dA0);
            fma2(accO[0], m0a.x, dA1); fma2(accO[1], m0a.y, dA1);
            fma2(accO[2], m0b.x, dA1); fma2(accO[3], m0b.y, dA1);
            fma2(accE[0], m1a.x, dB0); fma2(accE[1], m1a.y, dB0);
            fma2(accE[2], m1b.x, dB0); fma2(accE[3], m1b.y, dB0);
            fma2(accO[0], m1a.x, dB1); fma2(accO[1], m1a.y, dB1);
            fma2(accO[2], m1b.x, dB1); fma2(accO[3], m1b.y, dB1);
        }

        // epilogue: bias + leaky, coalesced float2 rows
        const int bg = b0 + lane;
        const int g = bg >> 9, d = bg & 511;
        float* op = out + ((size_t)(g * 128 + o0)) * 1024 + 2 * d;
#pragma unroll
        for (int p = 0; p < 4; ++p) {
            float e0 = f2lo(accE[p]) + tb[2 * p];
            float q0 = f2lo(accO[p]) + tb[2 * p];
            float e1 = f2hi(accE[p]) + tb[2 * p + 1];
            float q1 = f2hi(accO[p]) + tb[2 * p + 1];
            e0 = e0 > 0.f ? e0 : 0.01f * e0;
            q0 = q0 > 0.f ? q0 : 0.01f * q0;
            e1 = e1 > 0.f ? e1 : 0.01f * e1;
            q1 = q1 > 0.f ? q1 : 0.01f * q1;
            *(float2*)(op + (size_t)(2 * p) * 1024) = make_float2(e0, q0);
            *(float2*)(op + (size_t)(2 * p + 1) * 1024) = make_float2(e1, q1);
        }
    }
}

// ---------------- launch ----------------
extern "C" void kernel_launch(void* const* d_in, const int* in_sizes, int n_in,
                              void* d_out, int out_size) {
    const float* x = (const float*)d_in[0];
    const float* y = (const float*)d_in[1];
    const float* Wq = (const float*)d_in[2];
    const float* Wk = (const float*)d_in[3];
    const float* Wv = (const float*)d_in[4];
    const float* conv_w = (const float*)d_in[5];
    const float* conv_b = (const float*)d_in[6];
    const float* gamma = (const float*)d_in[7];
    const float* beta = (const float*)d_in[8];
    const float* mean = (const float*)d_in[9];
    const float* var = (const float*)d_in[10];
    const int B = in_sizes[0] / (4 * K);

    const size_t attn_smem = (size_t)(16384 + 8192 + 2048) * sizeof(float);  // 106496
    const size_t z_smem = (size_t)(3 * 16384) * sizeof(float);               // 196608
    cudaFuncSetAttribute(attn_kernel, cudaFuncAttributeMaxDynamicSharedMemorySize, (int)attn_smem);
    cudaFuncSetAttribute(z_kernel, cudaFuncAttributeMaxDynamicSharedMemorySize, (int)z_smem);

    setup_kernel<<<dim3(K, 3), 256>>>(Wq, Wk, Wv, conv_w, conv_b, gamma, beta, mean, var);
    attn_kernel<<<296, 256, attn_smem>>>(x, y, B);
    z_kernel<<<148, 512, z_smem>>>(x, (float*)d_out, B);
}